// round 3
// baseline (speedup 1.0000x reference)
#include <cuda_runtime.h>
#include <math_constants.h>

// ---------------------------------------------------------------------------
// Quantization4bit: global min/max -> affine normalize to [-1,1] -> nearest
// codebook value (14 entries, sorted ascending; harness materializes the fp16
// codebook as fp32 and the fp16 output as fp32).
//
// Pass 1: deterministic global min/max via order-preserving uint atomics.
// Pass 2: per-element interval search over the n_cb-1 fp32 midpoints
//         (== argmin of fp32 |x_norm - c| with first-index tie-break),
//         branchless selects, codebook length taken from in_sizes[1].
// ---------------------------------------------------------------------------

#define MAX_CB 16

__device__ unsigned g_min_u;
__device__ unsigned g_max_u;

// monotonic float -> uint mapping (total order)
__device__ __forceinline__ unsigned f2ord(float f) {
    unsigned u = __float_as_uint(f);
    return (u & 0x80000000u) ? ~u : (u | 0x80000000u);
}
__device__ __forceinline__ float ord2f(unsigned u) {
    u = (u & 0x80000000u) ? (u & 0x7fffffffu) : ~u;
    return __uint_as_float(u);
}

__global__ void q4_init_kernel() {
    g_min_u = 0xFFFFFFFFu;  // +inf in ordered space
    g_max_u = 0u;           // -inf in ordered space
}

__global__ void q4_minmax_kernel(const float4* __restrict__ x, int n4) {
    int tid = blockIdx.x * blockDim.x + threadIdx.x;
    int stride = gridDim.x * blockDim.x;

    float lmin = CUDART_INF_F;
    float lmax = -CUDART_INF_F;

    for (int i = tid; i < n4; i += stride) {
        float4 v = x[i];
        lmin = fminf(lmin, fminf(fminf(v.x, v.y), fminf(v.z, v.w)));
        lmax = fmaxf(lmax, fmaxf(fmaxf(v.x, v.y), fmaxf(v.z, v.w)));
    }

    #pragma unroll
    for (int o = 16; o > 0; o >>= 1) {
        lmin = fminf(lmin, __shfl_xor_sync(0xFFFFFFFFu, lmin, o));
        lmax = fmaxf(lmax, __shfl_xor_sync(0xFFFFFFFFu, lmax, o));
    }

    if ((threadIdx.x & 31) == 0) {
        atomicMin(&g_min_u, f2ord(lmin));
        atomicMax(&g_max_u, f2ord(lmax));
    }
}

__global__ void q4_quant_kernel(const float4* __restrict__ x,
                                const float* __restrict__ cb, int n_cb,
                                float4* __restrict__ out, int n4) {
    float xmin = ord2f(g_min_u);
    float xmax = ord2f(g_max_u);

    // x_norm = (x - xmin) / (xmax - xmin) * 2 - 1
    // (t*2 is exact, so fmaf(t,2,-1) rounds identically to (t*2)-1)
    float inv = 1.0f / (xmax - xmin);

    // codebook -> registers; pad tail so the unrolled chain is inert there
    float c[MAX_CB];
    #pragma unroll
    for (int i = 0; i < MAX_CB; i++)
        c[i] = (i < n_cb) ? cb[i] : CUDART_INF_F;

    float mid[MAX_CB - 1];
    #pragma unroll
    for (int j = 0; j < MAX_CB - 1; j++)
        mid[j] = (j + 1 < n_cb) ? 0.5f * (c[j] + c[j + 1]) : CUDART_INF_F;

    int tid = blockIdx.x * blockDim.x + threadIdx.x;
    int stride = gridDim.x * blockDim.x;

    for (int i = tid; i < n4; i += stride) {
        float4 v = x[i];
        float xs[4] = {v.x, v.y, v.z, v.w};
        float r[4];
        #pragma unroll
        for (int k = 0; k < 4; k++) {
            float t = (xs[k] - xmin) * inv;
            float xn = fmaf(t, 2.0f, -1.0f);
            float val = c[0];
            // strict > : at an exact midpoint the LOWER index wins,
            // matching argmin's first-minimum tie-break.
            #pragma unroll
            for (int j = 0; j < MAX_CB - 1; j++) {
                val = (xn > mid[j]) ? c[j + 1] : val;
            }
            r[k] = val;
        }
        out[i] = make_float4(r[0], r[1], r[2], r[3]);
    }
}

extern "C" void kernel_launch(void* const* d_in, const int* in_sizes, int n_in,
                              void* d_out, int out_size) {
    const float4* x = (const float4*)d_in[0];
    const float* cb = (const float*)d_in[1];
    float4* out = (float4*)d_out;

    int n = in_sizes[0];      // 2048*4096 = 8388608, divisible by 4
    int n_cb = in_sizes[1];   // 14 (reference comment says 15; code yields 14)
    if (n_cb > MAX_CB) n_cb = MAX_CB;
    int n4 = n >> 2;

    const int threads = 256;
    const int grid = 1184;    // ~8 blocks per SM

    q4_init_kernel<<<1, 1>>>();
    q4_minmax_kernel<<<grid, threads>>>(x, n4);
    q4_quant_kernel<<<grid, threads>>>(x, cb, n_cb, out, n4);
}

// round 4
// speedup vs baseline: 1.1493x; 1.1493x over previous
#include <cuda_runtime.h>
#include <math_constants.h>

// ---------------------------------------------------------------------------
// Quantization4bit, single persistent kernel:
//   phase 1: per-block min/max partials (grid-stride, float4, unroll-4)
//   grid barrier: monotonic counter/epoch (replay-safe, no reset kernel)
//   phase 2: affine normalize + nearest-of-14 codebook via branchless
//            midpoint chain (bit-identical to the R3 formulation, rel_err 0)
// All blocks are co-resident (296 blocks x 256 thr on 148+ SMs), so the
// spin barrier cannot deadlock. No atomim-order dependence -> deterministic.
// ---------------------------------------------------------------------------

#define MAX_CB 16
#define NBLK 296
#define NTHR 256

__device__ float g_pmin[NBLK];
__device__ float g_pmax[NBLK];
__device__ float g_final_min;
__device__ float g_final_max;
__device__ unsigned g_counter = 0;   // monotonic arrivals (never reset)
__device__ unsigned g_release = 0;   // monotonic release epoch

__global__ void __launch_bounds__(NTHR, 2)
q4_fused_kernel(const float4* __restrict__ x,
                const float* __restrict__ cb, int n_cb,
                float4* __restrict__ out, int n4) {
    __shared__ float s_red[NTHR / 32];
    __shared__ float s_red2[NTHR / 32];
    __shared__ unsigned s_epoch;
    __shared__ int s_last;

    const int tid = blockIdx.x * NTHR + threadIdx.x;
    const int stride = NBLK * NTHR;
    const int lane = threadIdx.x & 31;
    const int warp = threadIdx.x >> 5;

    // ---------------- phase 1: local min/max ----------------
    float lmin = CUDART_INF_F;
    float lmax = -CUDART_INF_F;

    int i = tid;
    for (; i + 3 * stride < n4; i += 4 * stride) {
        float4 v0 = x[i];
        float4 v1 = x[i + stride];
        float4 v2 = x[i + 2 * stride];
        float4 v3 = x[i + 3 * stride];
        float mn0 = fminf(fminf(v0.x, v0.y), fminf(v0.z, v0.w));
        float mx0 = fmaxf(fmaxf(v0.x, v0.y), fmaxf(v0.z, v0.w));
        float mn1 = fminf(fminf(v1.x, v1.y), fminf(v1.z, v1.w));
        float mx1 = fmaxf(fmaxf(v1.x, v1.y), fmaxf(v1.z, v1.w));
        float mn2 = fminf(fminf(v2.x, v2.y), fminf(v2.z, v2.w));
        float mx2 = fmaxf(fmaxf(v2.x, v2.y), fmaxf(v2.z, v2.w));
        float mn3 = fminf(fminf(v3.x, v3.y), fminf(v3.z, v3.w));
        float mx3 = fmaxf(fmaxf(v3.x, v3.y), fmaxf(v3.z, v3.w));
        lmin = fminf(lmin, fminf(fminf(mn0, mn1), fminf(mn2, mn3)));
        lmax = fmaxf(lmax, fmaxf(fmaxf(mx0, mx1), fmaxf(mx2, mx3)));
    }
    for (; i < n4; i += stride) {
        float4 v = x[i];
        lmin = fminf(lmin, fminf(fminf(v.x, v.y), fminf(v.z, v.w)));
        lmax = fmaxf(lmax, fmaxf(fmaxf(v.x, v.y), fmaxf(v.z, v.w)));
    }

    // warp reduce
    #pragma unroll
    for (int o = 16; o > 0; o >>= 1) {
        lmin = fminf(lmin, __shfl_xor_sync(0xFFFFFFFFu, lmin, o));
        lmax = fmaxf(lmax, __shfl_xor_sync(0xFFFFFFFFu, lmax, o));
    }
    if (lane == 0) { s_red[warp] = lmin; s_red2[warp] = lmax; }
    __syncthreads();

    // block reduce + arrival
    if (threadIdx.x == 0) {
        float bmin = s_red[0], bmax = s_red2[0];
        #pragma unroll
        for (int w = 1; w < NTHR / 32; w++) {
            bmin = fminf(bmin, s_red[w]);
            bmax = fmaxf(bmax, s_red2[w]);
        }
        g_pmin[blockIdx.x] = bmin;
        g_pmax[blockIdx.x] = bmax;
        __threadfence();
        unsigned old = atomicAdd(&g_counter, 1u);
        s_epoch = old / NBLK;                 // same for all blocks this run
        s_last = ((old % NBLK) == NBLK - 1);  // last arriver this run
    }
    __syncthreads();

    const unsigned epoch = s_epoch;

    if (s_last) {
        // last block reduces the partials and publishes
        float bmin = CUDART_INF_F, bmax = -CUDART_INF_F;
        for (int j = threadIdx.x; j < NBLK; j += NTHR) {
            bmin = fminf(bmin, g_pmin[j]);
            bmax = fmaxf(bmax, g_pmax[j]);
        }
        #pragma unroll
        for (int o = 16; o > 0; o >>= 1) {
            bmin = fminf(bmin, __shfl_xor_sync(0xFFFFFFFFu, bmin, o));
            bmax = fmaxf(bmax, __shfl_xor_sync(0xFFFFFFFFu, bmax, o));
        }
        if (lane == 0) { s_red[warp] = bmin; s_red2[warp] = bmax; }
        __syncthreads();
        if (threadIdx.x == 0) {
            float fmn = s_red[0], fmx = s_red2[0];
            #pragma unroll
            for (int w = 1; w < NTHR / 32; w++) {
                fmn = fminf(fmn, s_red[w]);
                fmx = fmaxf(fmx, s_red2[w]);
            }
            g_final_min = fmn;
            g_final_max = fmx;
            __threadfence();
            atomicAdd(&g_release, 1u);        // release -> epoch+1
        }
        __syncthreads();
    } else {
        // wait for release of this epoch
        if (threadIdx.x == 0) {
            while (*((volatile unsigned*)&g_release) < epoch + 1u)
                __nanosleep(64);
        }
        __syncthreads();
    }
    __threadfence();  // acquire side for g_final_min/max

    // ---------------- phase 2: quantize ----------------
    const float xmin = g_final_min;
    const float xmax = g_final_max;
    const float inv = 1.0f / (xmax - xmin);

    float c[MAX_CB];
    #pragma unroll
    for (int k = 0; k < MAX_CB; k++)
        c[k] = (k < n_cb) ? cb[k] : CUDART_INF_F;
    float mid[MAX_CB - 1];
    #pragma unroll
    for (int j = 0; j < MAX_CB - 1; j++)
        mid[j] = (j + 1 < n_cb) ? 0.5f * (c[j] + c[j + 1]) : CUDART_INF_F;

    for (int p = tid; p < n4; p += stride) {
        float4 v = x[p];
        float xs[4] = {v.x, v.y, v.z, v.w};
        float r[4];
        #pragma unroll
        for (int k = 0; k < 4; k++) {
            float t = (xs[k] - xmin) * inv;
            float xn = fmaf(t, 2.0f, -1.0f);
            float val = c[0];
            // strict > : exact-midpoint ties go to the LOWER index,
            // matching argmin's first-minimum tie-break.
            #pragma unroll
            for (int j = 0; j < MAX_CB - 1; j++)
                val = (xn > mid[j]) ? c[j + 1] : val;
            r[k] = val;
        }
        out[p] = make_float4(r[0], r[1], r[2], r[3]);
    }
}

extern "C" void kernel_launch(void* const* d_in, const int* in_sizes, int n_in,
                              void* d_out, int out_size) {
    const float4* x = (const float4*)d_in[0];
    const float* cb = (const float*)d_in[1];
    float4* out = (float4*)d_out;

    int n = in_sizes[0];      // 8388608
    int n_cb = in_sizes[1];   // 14
    if (n_cb > MAX_CB) n_cb = MAX_CB;
    int n4 = n >> 2;

    q4_fused_kernel<<<NBLK, NTHR>>>(x, cb, n_cb, out, n4);
}

// round 5
// speedup vs baseline: 1.3372x; 1.1635x over previous
#include <cuda_runtime.h>
#include <math_constants.h>

// ---------------------------------------------------------------------------
// Quantization4bit, single persistent kernel:
//   phase 1: per-block min/max partials (grid-stride, float4, unroll-4)
//   grid barrier: monotonic counter/epoch (replay-safe, no reset kernel)
//   phase 2: affine normalize + nearest-codebook via a 256-cell shared-memory
//            interval LUT. Each cell stores (mid, c_lo, c_hi): resolved cells
//            have mid=+inf. Result is bit-identical to the 14-deep midpoint
//            select chain (monotone cell map => class changes only inside the
//            cell containing a midpoint), i.e. fp32 |.| argmin, first-min ties.
// 592 blocks x 256 thr, <=4 blocks/SM guaranteed co-resident => barrier safe.
// ---------------------------------------------------------------------------

#define MAX_CB 16
#define NBLK 592
#define NTHR 256
#define NCELL 256

__device__ float g_pmin[NBLK];
__device__ float g_pmax[NBLK];
__device__ float g_final_min;
__device__ float g_final_max;
__device__ unsigned g_counter = 0;   // monotonic arrivals (never reset)
__device__ unsigned g_release = 0;   // monotonic release epoch

__global__ void __launch_bounds__(NTHR, 4)
q4_fused_kernel(const float4* __restrict__ x,
                const float* __restrict__ cb, int n_cb,
                float4* __restrict__ out, int n4) {
    __shared__ float4 s_tbl[NCELL];      // (mid, c_lo, c_hi, pad)
    __shared__ float s_red[NTHR / 32];
    __shared__ float s_red2[NTHR / 32];
    __shared__ unsigned s_epoch;
    __shared__ int s_last;

    const int tid = blockIdx.x * NTHR + threadIdx.x;
    const int stride = NBLK * NTHR;
    const int lane = threadIdx.x & 31;
    const int warp = threadIdx.x >> 5;

    // ---------------- phase 1: local min/max ----------------
    float lmin = CUDART_INF_F;
    float lmax = -CUDART_INF_F;

    int i = tid;
    for (; i + 3 * stride < n4; i += 4 * stride) {
        float4 v0 = x[i];
        float4 v1 = x[i + stride];
        float4 v2 = x[i + 2 * stride];
        float4 v3 = x[i + 3 * stride];
        float mn0 = fminf(fminf(v0.x, v0.y), fminf(v0.z, v0.w));
        float mx0 = fmaxf(fmaxf(v0.x, v0.y), fmaxf(v0.z, v0.w));
        float mn1 = fminf(fminf(v1.x, v1.y), fminf(v1.z, v1.w));
        float mx1 = fmaxf(fmaxf(v1.x, v1.y), fmaxf(v1.z, v1.w));
        float mn2 = fminf(fminf(v2.x, v2.y), fminf(v2.z, v2.w));
        float mx2 = fmaxf(fmaxf(v2.x, v2.y), fmaxf(v2.z, v2.w));
        float mn3 = fminf(fminf(v3.x, v3.y), fminf(v3.z, v3.w));
        float mx3 = fmaxf(fmaxf(v3.x, v3.y), fmaxf(v3.z, v3.w));
        lmin = fminf(lmin, fminf(fminf(mn0, mn1), fminf(mn2, mn3)));
        lmax = fmaxf(lmax, fmaxf(fmaxf(mx0, mx1), fmaxf(mx2, mx3)));
    }
    for (; i < n4; i += stride) {
        float4 v = x[i];
        lmin = fminf(lmin, fminf(fminf(v.x, v.y), fminf(v.z, v.w)));
        lmax = fmaxf(lmax, fmaxf(fmaxf(v.x, v.y), fmaxf(v.z, v.w)));
    }

    #pragma unroll
    for (int o = 16; o > 0; o >>= 1) {
        lmin = fminf(lmin, __shfl_xor_sync(0xFFFFFFFFu, lmin, o));
        lmax = fmaxf(lmax, __shfl_xor_sync(0xFFFFFFFFu, lmax, o));
    }
    if (lane == 0) { s_red[warp] = lmin; s_red2[warp] = lmax; }
    __syncthreads();

    if (threadIdx.x == 0) {
        float bmin = s_red[0], bmax = s_red2[0];
        #pragma unroll
        for (int w = 1; w < NTHR / 32; w++) {
            bmin = fminf(bmin, s_red[w]);
            bmax = fmaxf(bmax, s_red2[w]);
        }
        g_pmin[blockIdx.x] = bmin;
        g_pmax[blockIdx.x] = bmax;
        __threadfence();
        unsigned old = atomicAdd(&g_counter, 1u);
        s_epoch = old / NBLK;
        s_last = ((old % NBLK) == NBLK - 1);
    }
    __syncthreads();

    const unsigned epoch = s_epoch;

    if (s_last) {
        float bmin = CUDART_INF_F, bmax = -CUDART_INF_F;
        for (int j = threadIdx.x; j < NBLK; j += NTHR) {
            bmin = fminf(bmin, g_pmin[j]);
            bmax = fmaxf(bmax, g_pmax[j]);
        }
        #pragma unroll
        for (int o = 16; o > 0; o >>= 1) {
            bmin = fminf(bmin, __shfl_xor_sync(0xFFFFFFFFu, bmin, o));
            bmax = fmaxf(bmax, __shfl_xor_sync(0xFFFFFFFFu, bmax, o));
        }
        if (lane == 0) { s_red[warp] = bmin; s_red2[warp] = bmax; }
        __syncthreads();
        if (threadIdx.x == 0) {
            float fmn = s_red[0], fmx = s_red2[0];
            #pragma unroll
            for (int w = 1; w < NTHR / 32; w++) {
                fmn = fminf(fmn, s_red[w]);
                fmx = fmaxf(fmx, s_red2[w]);
            }
            g_final_min = fmn;
            g_final_max = fmx;
            __threadfence();
            atomicAdd(&g_release, 1u);
        }
        __syncthreads();
    } else {
        if (threadIdx.x == 0) {
            while (*((volatile unsigned*)&g_release) < epoch + 1u)
                __nanosleep(64);
        }
        __syncthreads();
    }
    __threadfence();  // acquire for g_final_min/max

    const float xmin = g_final_min;
    const float xmax = g_final_max;
    const float inv = 1.0f / (xmax - xmin);

    // ------------- build the interval LUT in shared memory -------------
    {
        float c[MAX_CB];
        #pragma unroll
        for (int k = 0; k < MAX_CB; k++)
            c[k] = (k < n_cb) ? cb[k] : CUDART_INF_F;
        float mid[MAX_CB - 1];
        #pragma unroll
        for (int j = 0; j < MAX_CB - 1; j++)
            mid[j] = (j + 1 < n_cb) ? 0.5f * (c[j] + c[j + 1]) : CUDART_INF_F;

        // default: classify cell center via the full chain (cells without a
        // midpoint are class-uniform by monotonicity of the cell map)
        for (int cell = threadIdx.x; cell < NCELL; cell += NTHR) {
            float xc = ((float)cell + 0.5f) * (2.0f / NCELL) - 1.0f;
            float val = c[0];
            #pragma unroll
            for (int j = 0; j < MAX_CB - 1; j++)
                val = (xc > mid[j]) ? c[j + 1] : val;
            s_tbl[cell] = make_float4(CUDART_INF_F, val, val, 0.0f);
        }
        __syncthreads();

        // overwrite the (distinct) cells containing a midpoint
        if (threadIdx.x < n_cb - 1) {
            float mj = mid[threadIdx.x];
            float u = fmaf(mj, (float)(NCELL / 2), (float)(NCELL / 2));
            int cell = (int)u;
            cell = (cell < 0) ? 0 : ((cell > NCELL - 1) ? NCELL - 1 : cell);
            s_tbl[cell] = make_float4(mj, c[threadIdx.x], c[threadIdx.x + 1], 0.0f);
        }
        __syncthreads();
    }

    // ---------------- phase 2: quantize via LUT ----------------
    for (int p = tid; p < n4; p += stride) {
        float4 v = x[p];
        float xs[4] = {v.x, v.y, v.z, v.w};
        float r[4];
        #pragma unroll
        for (int k = 0; k < 4; k++) {
            float t = (xs[k] - xmin) * inv;
            float xn = fmaf(t, 2.0f, -1.0f);              // exact same xn as chain version
            float u = fmaf(xn, (float)(NCELL / 2), (float)(NCELL / 2));
            int cell = (int)u;
            cell = (cell < 0) ? 0 : ((cell > NCELL - 1) ? NCELL - 1 : cell);
            float4 e = s_tbl[cell];
            // strict > : exact-midpoint ties go to the LOWER index (c_lo),
            // matching argmin's first-minimum tie-break.
            r[k] = (xn > e.x) ? e.z : e.y;
        }
        out[p] = make_float4(r[0], r[1], r[2], r[3]);
    }
}

extern "C" void kernel_launch(void* const* d_in, const int* in_sizes, int n_in,
                              void* d_out, int out_size) {
    const float4* x = (const float4*)d_in[0];
    const float* cb = (const float*)d_in[1];
    float4* out = (float4*)d_out;

    int n = in_sizes[0];      // 8388608
    int n_cb = in_sizes[1];   // 14
    if (n_cb > MAX_CB) n_cb = MAX_CB;
    int n4 = n >> 2;

    q4_fused_kernel<<<NBLK, NTHR>>>(x, cb, n_cb, out, n4);
}

// round 6
// speedup vs baseline: 1.4851x; 1.1106x over previous
#include <cuda_runtime.h>
#include <cuda_fp16.h>
#include <math_constants.h>

// ---------------------------------------------------------------------------
// Quantization4bit, single persistent kernel:
//   phase 1: per-block min/max partials (grid-stride, float4, unroll-4)
//   grid barrier: monotonic counter/epoch (replay-safe)
//   phase 2: affine normalize + nearest-codebook via a 256-cell, 8-byte/cell
//            shared-memory interval LUT: {mid fp32, half2(c_lo,c_hi)}.
//            Codebook values are fp16-originated, so half round-trip is
//            bit-exact; compare in fp32 => identical to the 14-deep midpoint
//            select chain (fp32 |.| argmin, first-min tie-break).
// 592 blocks x 256 thr, <=4 blocks/SM co-resident => barrier safe.
// ---------------------------------------------------------------------------

#define MAX_CB 16
#define NBLK 592
#define NTHR 256
#define NCELL 256

__device__ float g_pmin[NBLK];
__device__ float g_pmax[NBLK];
__device__ float g_final_min;
__device__ float g_final_max;
__device__ unsigned g_counter = 0;   // monotonic arrivals (never reset)
__device__ unsigned g_release = 0;   // monotonic release epoch

__device__ __forceinline__ float lut_pick(uint2 e, float xn) {
    float midv = __uint_as_float(e.x);
    // strict > : exact-midpoint ties go to the LOWER index (low half),
    // matching argmin's first-minimum tie-break.
    unsigned bits = (xn > midv) ? (e.y >> 16) : (e.y & 0xFFFFu);
    return __half2float(__ushort_as_half((unsigned short)bits));
}

__device__ __forceinline__ int cell_of(float xn) {
    float u = fmaf(xn, (float)(NCELL / 2), (float)(NCELL / 2));  // >= 0 by construction
    u = fminf(u, (float)(NCELL - 1));
    return (int)u;
}

__global__ void __launch_bounds__(NTHR, 4)
q4_fused_kernel(const float4* __restrict__ x,
                const float* __restrict__ cb, int n_cb,
                float4* __restrict__ out, int n4) {
    __shared__ uint2 s_tbl[NCELL];       // {mid fp32 bits, half2(c_lo,c_hi)}
    __shared__ float s_red[NTHR / 32];
    __shared__ float s_red2[NTHR / 32];
    __shared__ unsigned s_epoch;
    __shared__ int s_last;

    const int tid = blockIdx.x * NTHR + threadIdx.x;
    const int stride = NBLK * NTHR;
    const int lane = threadIdx.x & 31;
    const int warp = threadIdx.x >> 5;

    // ---------------- phase 1: local min/max ----------------
    float lmin = CUDART_INF_F;
    float lmax = -CUDART_INF_F;

    int i = tid;
    for (; i + 3 * stride < n4; i += 4 * stride) {
        float4 v0 = x[i];
        float4 v1 = x[i + stride];
        float4 v2 = x[i + 2 * stride];
        float4 v3 = x[i + 3 * stride];
        float mn0 = fminf(fminf(v0.x, v0.y), fminf(v0.z, v0.w));
        float mx0 = fmaxf(fmaxf(v0.x, v0.y), fmaxf(v0.z, v0.w));
        float mn1 = fminf(fminf(v1.x, v1.y), fminf(v1.z, v1.w));
        float mx1 = fmaxf(fmaxf(v1.x, v1.y), fmaxf(v1.z, v1.w));
        float mn2 = fminf(fminf(v2.x, v2.y), fminf(v2.z, v2.w));
        float mx2 = fmaxf(fmaxf(v2.x, v2.y), fmaxf(v2.z, v2.w));
        float mn3 = fminf(fminf(v3.x, v3.y), fminf(v3.z, v3.w));
        float mx3 = fmaxf(fmaxf(v3.x, v3.y), fmaxf(v3.z, v3.w));
        lmin = fminf(lmin, fminf(fminf(mn0, mn1), fminf(mn2, mn3)));
        lmax = fmaxf(lmax, fmaxf(fmaxf(mx0, mx1), fmaxf(mx2, mx3)));
    }
    for (; i < n4; i += stride) {
        float4 v = x[i];
        lmin = fminf(lmin, fminf(fminf(v.x, v.y), fminf(v.z, v.w)));
        lmax = fmaxf(lmax, fmaxf(fmaxf(v.x, v.y), fmaxf(v.z, v.w)));
    }

    #pragma unroll
    for (int o = 16; o > 0; o >>= 1) {
        lmin = fminf(lmin, __shfl_xor_sync(0xFFFFFFFFu, lmin, o));
        lmax = fmaxf(lmax, __shfl_xor_sync(0xFFFFFFFFu, lmax, o));
    }
    if (lane == 0) { s_red[warp] = lmin; s_red2[warp] = lmax; }
    __syncthreads();

    if (threadIdx.x == 0) {
        float bmin = s_red[0], bmax = s_red2[0];
        #pragma unroll
        for (int w = 1; w < NTHR / 32; w++) {
            bmin = fminf(bmin, s_red[w]);
            bmax = fmaxf(bmax, s_red2[w]);
        }
        g_pmin[blockIdx.x] = bmin;
        g_pmax[blockIdx.x] = bmax;
        __threadfence();
        unsigned old = atomicAdd(&g_counter, 1u);
        s_epoch = old / NBLK;
        s_last = ((old % NBLK) == NBLK - 1);
    }
    __syncthreads();

    const unsigned epoch = s_epoch;

    if (s_last) {
        float bmin = CUDART_INF_F, bmax = -CUDART_INF_F;
        for (int j = threadIdx.x; j < NBLK; j += NTHR) {
            bmin = fminf(bmin, g_pmin[j]);
            bmax = fmaxf(bmax, g_pmax[j]);
        }
        #pragma unroll
        for (int o = 16; o > 0; o >>= 1) {
            bmin = fminf(bmin, __shfl_xor_sync(0xFFFFFFFFu, bmin, o));
            bmax = fmaxf(bmax, __shfl_xor_sync(0xFFFFFFFFu, bmax, o));
        }
        if (lane == 0) { s_red[warp] = bmin; s_red2[warp] = bmax; }
        __syncthreads();
        if (threadIdx.x == 0) {
            float fmn = s_red[0], fmx = s_red2[0];
            #pragma unroll
            for (int w = 1; w < NTHR / 32; w++) {
                fmn = fminf(fmn, s_red[w]);
                fmx = fmaxf(fmx, s_red2[w]);
            }
            g_final_min = fmn;
            g_final_max = fmx;
            __threadfence();
            atomicAdd(&g_release, 1u);
        }
        __syncthreads();
    } else {
        if (threadIdx.x == 0) {
            while (*((volatile unsigned*)&g_release) < epoch + 1u)
                __nanosleep(64);
        }
        __syncthreads();
    }
    __threadfence();  // acquire for g_final_min/max

    const float xmin = g_final_min;
    const float xmax = g_final_max;
    const float inv = 1.0f / (xmax - xmin);

    // ------------- build the 8B/cell interval LUT -------------
    {
        float c[MAX_CB];
        #pragma unroll
        for (int k = 0; k < MAX_CB; k++)
            c[k] = (k < n_cb) ? cb[k] : CUDART_INF_F;
        float mid[MAX_CB - 1];
        #pragma unroll
        for (int j = 0; j < MAX_CB - 1; j++)
            mid[j] = (j + 1 < n_cb) ? 0.5f * (c[j] + c[j + 1]) : CUDART_INF_F;

        for (int cell = threadIdx.x; cell < NCELL; cell += NTHR) {
            float xc = ((float)cell + 0.5f) * (2.0f / NCELL) - 1.0f;
            float val = c[0];
            #pragma unroll
            for (int j = 0; j < MAX_CB - 1; j++)
                val = (xc > mid[j]) ? c[j + 1] : val;
            __half2 pr = __floats2half2_rn(val, val);  // exact: fp16-originated
            s_tbl[cell] = make_uint2(__float_as_uint(CUDART_INF_F),
                                     *(unsigned*)&pr);
        }
        __syncthreads();

        if (threadIdx.x < n_cb - 1) {
            float mj = mid[threadIdx.x];
            int cell = cell_of(mj);
            __half2 pr = __floats2half2_rn(c[threadIdx.x], c[threadIdx.x + 1]);
            s_tbl[cell] = make_uint2(__float_as_uint(mj), *(unsigned*)&pr);
        }
        __syncthreads();
    }

    // ---------------- phase 2: quantize via LUT, unroll 2 ----------------
    int p = tid;
    for (; p + stride < n4; p += 2 * stride) {
        float4 v0 = x[p];
        float4 v1 = x[p + stride];
        float a0[4] = {v0.x, v0.y, v0.z, v0.w};
        float a1[4] = {v1.x, v1.y, v1.z, v1.w};
        float r0[4], r1[4];
        #pragma unroll
        for (int k = 0; k < 4; k++) {
            float t0 = (a0[k] - xmin) * inv;
            float t1 = (a1[k] - xmin) * inv;
            float xn0 = fmaf(t0, 2.0f, -1.0f);
            float xn1 = fmaf(t1, 2.0f, -1.0f);
            uint2 e0 = s_tbl[cell_of(xn0)];
            uint2 e1 = s_tbl[cell_of(xn1)];
            r0[k] = lut_pick(e0, xn0);
            r1[k] = lut_pick(e1, xn1);
        }
        __stcs(&out[p], make_float4(r0[0], r0[1], r0[2], r0[3]));
        __stcs(&out[p + stride], make_float4(r1[0], r1[1], r1[2], r1[3]));
    }
    for (; p < n4; p += stride) {
        float4 v = x[p];
        float a0[4] = {v.x, v.y, v.z, v.w};
        float r0[4];
        #pragma unroll
        for (int k = 0; k < 4; k++) {
            float t = (a0[k] - xmin) * inv;
            float xn = fmaf(t, 2.0f, -1.0f);
            uint2 e = s_tbl[cell_of(xn)];
            r0[k] = lut_pick(e, xn);
        }
        __stcs(&out[p], make_float4(r0[0], r0[1], r0[2], r0[3]));
    }
}

extern "C" void kernel_launch(void* const* d_in, const int* in_sizes, int n_in,
                              void* d_out, int out_size) {
    const float4* x = (const float4*)d_in[0];
    const float* cb = (const float*)d_in[1];
    float4* out = (float4*)d_out;

    int n = in_sizes[0];      // 8388608
    int n_cb = in_sizes[1];   // 14
    if (n_cb > MAX_CB) n_cb = MAX_CB;
    int n4 = n >> 2;

    q4_fused_kernel<<<NBLK, NTHR>>>(x, cb, n_cb, out, n4);
}